// round 11
// baseline (speedup 1.0000x reference)
#include <cuda_runtime.h>
#include <cuda_bf16.h>

// NeuronGemma4VisionPooler: B=8, S=4096, H=1152, L=256, k=4, k_sq=16
// hidden_states f32 [B,S,H]; pixel_position_ids i32 [B,S,2];
// padding_positions bool [B,S]; out: pooled f32 [B,L,H] (+ mask [B,L] f32)

#define BB 8
#define SS 4096
#define HH 1152
#define LL 256
#define KK 4
#define CAP 64          // max recorded tokens per bin (expected 16)
#define NBIN (BB * LL)  // 2048 output bins
#define NPOOL 888       // persistent pool grid: 148 SMs * 6 CTAs (one wave)
#define MAXB 3          // max bins per CTA: ceil(2048/888)

// Invariant: g_count is all-zero at entry to kernel_launch.
// (.bss zero at module load for the 1st call; k_pool resets it every call.)
__device__ int g_count[NBIN];          // packed: [total<<16 | appended]
__device__ int g_inv[NBIN * CAP];

// --- K1: parallel prologue. 8 blocks per batch (64 total).
__global__ void __launch_bounds__(512)
k_prep(const int* __restrict__ pos, const unsigned char* __restrict__ pad) {
    const int b     = blockIdx.x >> 3;
    const int slice = blockIdx.x & 7;
    const int t     = threadIdx.x;
    const int2* __restrict__ p2 = (const int2*)pos + (size_t)b * SS;

    // max over clamped x for the whole batch (redundant per block; L2-hot)
    int m = 0;
    #pragma unroll
    for (int s = t; s < SS; s += 512) {
        int x = p2[s].x;
        if (x > m) m = x;                       // clip(x,0): negatives lose
    }
    #pragma unroll
    for (int o = 16; o; o >>= 1) m = max(m, __shfl_xor_sync(0xffffffffu, m, o));
    __shared__ int s_red[16];
    __shared__ int s_mxk;
    if ((t & 31) == 0) s_red[t >> 5] = m;
    __syncthreads();
    if (t < 16) {
        int v = s_red[t];
        #pragma unroll
        for (int o = 8; o; o >>= 1) v = max(v, __shfl_xor_sync(0xffffu, v, o));
        if (t == 0) s_mxk = (v + 1) / KK;        // (max_clamped+1)/k
    }
    __syncthreads();
    const int mxk = s_mxk;

    // bin this block's 512-token slice (one token per thread)
    const int s = slice * 512 + t;
    int2 p = p2[s];
    int x = max(p.x, 0);
    int y = max(p.y, 0);
    int idx = x / KK + mxk * (y / KK);
    if (idx < LL) {                              // one_hot drops idx >= L
        if (pad[(size_t)b * SS + s]) {
            atomicAdd(&g_count[b * LL + idx], 0x10000);   // total only (mask)
        } else {
            int old = atomicAdd(&g_count[b * LL + idx], 0x10001);
            int slot = old & 0xffff;
            if (slot < CAP)
                g_inv[(b * LL + idx) * CAP + slot] = s;
        }
    }
}

// --- K2: persistent pool. CTA c owns bins {c, c+888, c+1776} (<2048).
// All bin indices staged to smem with ONE barrier, then bins processed
// back-to-back (no inter-bin barriers). PDL: overlaps launch with k_prep.
__global__ void __launch_bounds__(288, 6)
k_pool(const float* __restrict__ hs, float* __restrict__ out, int write_mask) {
    const int c = blockIdx.x;
    const int t = threadIdx.x;                   // 0..287 = H/4 lanes
    __shared__ int sidx[MAXB][CAP];
    __shared__ int scnt[MAXB];

    const int nb = (c + 2 * NPOOL < NBIN) ? 3 : 2;   // bins this CTA owns

    // wait for k_prep's results (programmatic dependent launch)
    cudaGridDependencySynchronize();

    // stage all owned bins' indices + counts; single barrier
    if (t < MAXB * CAP) {
        int k = t >> 6, j = t & 63;
        if (k < nb) sidx[k][j] = g_inv[(c + k * NPOOL) * CAP + j];
    } else if (t >= 284 && t - 284 < nb) {
        int k = t - 284;
        int bin = c + k * NPOOL;
        scnt[k] = g_count[bin];
        g_count[bin] = 0;                        // reset for next launch
    }
    __syncthreads();

    const float scale = 2.1213203435596424f;     // sqrt(1152)/16
    #pragma unroll
    for (int k = 0; k < MAXB; k++) {
        if (k >= nb) break;
        const int bin = c + k * NPOOL;
        const int packed = scnt[k];
        const int n = min(packed & 0xffff, CAP);
        const float4* __restrict__ base =
            (const float4*)hs + (size_t)(bin >> 8) * SS * (HH / 4);

        float4 acc = make_float4(0.f, 0.f, 0.f, 0.f);
        if (n == 16) {
            #pragma unroll
            for (int j = 0; j < 16; j++) {
                float4 v = __ldg(&base[(size_t)sidx[k][j] * (HH / 4) + t]);
                acc.x += v.x; acc.y += v.y; acc.z += v.z; acc.w += v.w;
            }
        } else {
            for (int j = 0; j < n; j++) {
                float4 v = __ldg(&base[(size_t)sidx[k][j] * (HH / 4) + t]);
                acc.x += v.x; acc.y += v.y; acc.z += v.z; acc.w += v.w;
            }
        }
        acc.x *= scale; acc.y *= scale; acc.z *= scale; acc.w *= scale;
        ((float4*)out)[(size_t)bin * (HH / 4) + t] = acc;
        if (write_mask && t == 0)
            out[(size_t)NBIN * HH + bin] = ((packed >> 16) > 0) ? 1.0f : 0.0f;
    }
}

extern "C" void kernel_launch(void* const* d_in, const int* in_sizes, int n_in,
                              void* d_out, int out_size) {
    const float*         hs  = (const float*)d_in[0];
    const int*           pos = (const int*)d_in[1];
    const unsigned char* pad = (const unsigned char*)d_in[2];
    float* out = (float*)d_out;

    int write_mask = (out_size >= NBIN * HH + NBIN) ? 1 : 0;

    k_prep<<<BB * 8, 512>>>(pos, pad);

    // PDL launch: k_pool may begin while k_prep drains; it gates on
    // cudaGridDependencySynchronize() before reading prep results.
    cudaLaunchConfig_t cfg = {};
    cfg.gridDim  = dim3(NPOOL, 1, 1);
    cfg.blockDim = dim3(288, 1, 1);
    cudaLaunchAttribute at[1];
    at[0].id = cudaLaunchAttributeProgrammaticStreamSerialization;
    at[0].val.programmaticStreamSerializationAllowed = 1;
    cfg.attrs = at;
    cfg.numAttrs = 1;
    cudaLaunchKernelEx(&cfg, k_pool, hs, out, write_mask);
}